// round 16
// baseline (speedup 1.0000x reference)
#include <cuda_runtime.h>
#include <cuda_fp16.h>
#include <cstdint>

#define NN 100000
#define NE 1200000
#define NG 256
#define HID 64
#define INC 5
#define NBLK ((NN + 255) / 256)

// -------- scratch (device globals; no allocation allowed) --------
__device__ __align__(256) __half g_xpre[NN * 8];     // dinv*x, 5 used of 8 halves
__device__ __align__(256) float  g_aggx[NN * 8];     // layer-1 aggregated input (5 used)
__device__ __align__(256) __half g_h1[NN * HID];     // h1pre = dinv*relu(lin1) fp16
__device__ __align__(256) float  g_aggh[NN * HID];   // layer-2 aggregated hidden
__device__ __align__(256) int    g_degi[NN];
__device__ __align__(256) int    g_rowptr[NN];
__device__ __align__(256) int    g_cursor[NN];
__device__ __align__(256) float  g_dinv[NN];
__device__ __align__(256) int    g_csri[NE];         // src per edge, dst-grouped
__device__ __align__(256) float  g_pooled[NG * HID];
__device__ __align__(256) float  g_cnt[NG];
__device__ int g_gbase;

__device__ __forceinline__ void red4(float* p, float a, float b, float c, float d) {
    asm volatile("red.global.add.v4.f32 [%0], {%1,%2,%3,%4};"
                 :: "l"(p), "f"(a), "f"(b), "f"(c), "f"(d) : "memory");
}

// -------- init --------
__global__ void k_init() {
    int i = blockIdx.x * blockDim.x + threadIdx.x;
    if (i < NN) g_degi[i] = 0;
    if (i < NG * HID) g_pooled[i] = 0.f;
    if (i < NG) g_cnt[i] = 0.f;
    if (i == 0) g_gbase = 0;
}

// -------- degree (no return value -> REDG path) --------
__global__ void k_degi(const int* __restrict__ dst) {
    int e = blockIdx.x * blockDim.x + threadIdx.x;
    if (e >= NE) return;
    atomicAdd(&g_degi[dst[e]], 1);
}

// -------- single-pass scan (block scan + atomic base) + node prep --------
__global__ void k_scan(const float* __restrict__ x, const int* __restrict__ batch) {
    __shared__ int sh[256];
    __shared__ int sbase;
    int i = blockIdx.x * 256 + threadIdx.x;
    int v = (i < NN) ? g_degi[i] : 0;
    sh[threadIdx.x] = v;
    __syncthreads();
    for (int off = 1; off < 256; off <<= 1) {
        int t = (threadIdx.x >= off) ? sh[threadIdx.x - off] : 0;
        __syncthreads();
        sh[threadIdx.x] += t;
        __syncthreads();
    }
    if (threadIdx.x == 255) sbase = atomicAdd(&g_gbase, sh[255]);
    __syncthreads();
    if (i >= NN) return;
    int r = sbase + sh[threadIdx.x] - v;
    g_rowptr[i] = r;
    g_cursor[i] = r;
    float di = rsqrtf((float)v + 1.0f);       // +1 = self-loop
    g_dinv[i] = di;
    const float* xr = x + i * INC;
    __half2 h0 = __floats2half2_rn(di * __ldg(xr + 0), di * __ldg(xr + 1));
    __half2 h1 = __floats2half2_rn(di * __ldg(xr + 2), di * __ldg(xr + 3));
    __half2 h2 = __floats2half2_rn(di * __ldg(xr + 4), 0.f);
    uint4 u;
    u.x = *(unsigned*)&h0; u.y = *(unsigned*)&h1;
    u.z = *(unsigned*)&h2; u.w = 0u;
    *(uint4*)(g_xpre + i * 8) = u;
    atomicAdd(&g_cnt[__ldg(batch + i)], 1.0f);
}

// -------- scatter edges into CSR slots (cursor atomic) --------
__global__ void k_scatter(const int* __restrict__ src, const int* __restrict__ dst) {
    int e = blockIdx.x * blockDim.x + threadIdx.x;
    if (e >= NE) return;
    int s = __ldg(src + e);
    int d = __ldg(dst + e);
    int slot = atomicAdd(&g_cursor[d], 1);
    g_csri[slot] = s;
}

__device__ __forceinline__ void acc5(uint4 u, float a[5]) {
    float2 f0 = __half22float2(*(__half2*)&u.x);
    float2 f1 = __half22float2(*(__half2*)&u.y);
    float2 f2 = __half22float2(*(__half2*)&u.z);
    a[0] += f0.x; a[1] += f0.y; a[2] += f1.x; a[3] += f1.y; a[4] += f2.x;
}

// -------- layer-1 aggregation: ONE WARP PER NODE --------
// Each lane grabs edge (beg+lane, +32, ...); butterfly-reduce; lane 0 writes.
__global__ void __launch_bounds__(256) k_aggx() {
    int t = blockIdx.x * 256 + threadIdx.x;
    int n = t >> 5;                     // warp per node; grid exact (NN*32)
    if (n >= NN) return;
    int lane = threadIdx.x & 31;
    int beg = g_rowptr[n];
    int end = beg + g_degi[n];
    float a[5] = {0.f, 0.f, 0.f, 0.f, 0.f};
    for (int j = beg + lane; j < end; j += 32)
        acc5(__ldg((const uint4*)(g_xpre + __ldg(g_csri + j) * 8)), a);
#pragma unroll
    for (int c = 0; c < 5; c++) {
        a[c] += __shfl_xor_sync(0xffffffffu, a[c], 16);
        a[c] += __shfl_xor_sync(0xffffffffu, a[c], 8);
        a[c] += __shfl_xor_sync(0xffffffffu, a[c], 4);
        a[c] += __shfl_xor_sync(0xffffffffu, a[c], 2);
        a[c] += __shfl_xor_sync(0xffffffffu, a[c], 1);
    }
    if (lane == 0) {
        acc5(*(const uint4*)(g_xpre + n * 8), a);   // self term
        float di = g_dinv[n];
        float* o = g_aggx + n * 8;
        *(float4*)o = make_float4(di * a[0], di * a[1], di * a[2], di * a[3]);
        o[4] = di * a[4];
    }
}

// -------- lin1: h1pre = dinv * relu(aggX @ W1 + b1) -> fp16; 8 ch/thread --
__global__ void k_lin1(const float* __restrict__ W1, const float* __restrict__ b1) {
    int idx = blockIdx.x * blockDim.x + threadIdx.x;   // NN*8 threads
    if (idx >= NN * 8) return;
    int n = idx >> 3, c8 = (idx & 7) * 8;
    float xr[INC];
#pragma unroll
    for (int k = 0; k < INC; k++) xr[k] = __ldg(g_aggx + n * 8 + k);
    float4 a0 = __ldg((const float4*)(b1 + c8));
    float4 a1 = __ldg((const float4*)(b1 + c8 + 4));
#pragma unroll
    for (int k = 0; k < INC; k++) {
        float4 w0 = __ldg((const float4*)(W1 + k * HID + c8));
        float4 w1 = __ldg((const float4*)(W1 + k * HID + c8 + 4));
        a0.x = fmaf(xr[k], w0.x, a0.x); a0.y = fmaf(xr[k], w0.y, a0.y);
        a0.z = fmaf(xr[k], w0.z, a0.z); a0.w = fmaf(xr[k], w0.w, a0.w);
        a1.x = fmaf(xr[k], w1.x, a1.x); a1.y = fmaf(xr[k], w1.y, a1.y);
        a1.z = fmaf(xr[k], w1.z, a1.z); a1.w = fmaf(xr[k], w1.w, a1.w);
    }
    float di = g_dinv[n];
    __half2 p0 = __floats2half2_rn(di * fmaxf(a0.x, 0.f), di * fmaxf(a0.y, 0.f));
    __half2 p1 = __floats2half2_rn(di * fmaxf(a0.z, 0.f), di * fmaxf(a0.w, 0.f));
    __half2 p2 = __floats2half2_rn(di * fmaxf(a1.x, 0.f), di * fmaxf(a1.y, 0.f));
    __half2 p3 = __floats2half2_rn(di * fmaxf(a1.z, 0.f), di * fmaxf(a1.w, 0.f));
    uint4 u;
    u.x = *(unsigned*)&p0; u.y = *(unsigned*)&p1;
    u.z = *(unsigned*)&p2; u.w = *(unsigned*)&p3;
    *(uint4*)(g_h1 + (size_t)n * HID + c8) = u;
}

__device__ __forceinline__ void acc8(uint4 u, float a[8]) {
    float2 f0 = __half22float2(*(__half2*)&u.x);
    float2 f1 = __half22float2(*(__half2*)&u.y);
    float2 f2 = __half22float2(*(__half2*)&u.z);
    float2 f3 = __half22float2(*(__half2*)&u.w);
    a[0] += f0.x; a[1] += f0.y; a[2] += f1.x; a[3] += f1.y;
    a[4] += f2.x; a[5] += f2.y; a[6] += f3.x; a[7] += f3.y;
}

// -------- layer-2 aggregation: ONE WARP PER NODE --------
// Lanes = 4 edge-slots x 8 channel-lanes; 4 edge rows in flight per iter;
// cross-slot shfl reduce; edge-slot 0 writes the 256B row.
__global__ void __launch_bounds__(256) k_aggh() {
    int t = blockIdx.x * 256 + threadIdx.x;
    int n = t >> 5;                     // warp per node; grid exact (NN*32)
    if (n >= NN) return;
    int lane = threadIdx.x & 31;
    int es = lane >> 3;                 // edge slot 0..3
    int l = (lane & 7) * 8;             // channel base
    int beg = g_rowptr[n];
    int end = beg + g_degi[n];
    float a[8] = {0.f, 0.f, 0.f, 0.f, 0.f, 0.f, 0.f, 0.f};
    for (int j = beg + es; j < end; j += 4) {
        int s = __ldg(g_csri + j);      // same j for 8 ch-lanes -> broadcast
        acc8(__ldg((const uint4*)(g_h1 + (size_t)s * HID + l)), a);
    }
    if (es == 0)                        // self term once
        acc8(*(const uint4*)(g_h1 + (size_t)n * HID + l), a);
#pragma unroll
    for (int c = 0; c < 8; c++) {
        a[c] += __shfl_xor_sync(0xffffffffu, a[c], 8);
        a[c] += __shfl_xor_sync(0xffffffffu, a[c], 16);
    }
    if (es == 0) {
        float di = g_dinv[n];
        float* o = g_aggh + (size_t)n * HID + l;
        *(float4*)o       = make_float4(di * a[0], di * a[1], di * a[2], di * a[3]);
        *(float4*)(o + 4) = make_float4(di * a[4], di * a[5], di * a[6], di * a[7]);
    }
}

// -------- lin2 fused with relu + mean-pool RED (no h2 buffer) -------------
__global__ void __launch_bounds__(128) k_lin2pool(const float* __restrict__ W2,
                                                  const float* __restrict__ b2,
                                                  const int* __restrict__ batch) {
    __shared__ float Ws[HID * HID];
    for (int i = threadIdx.x; i < HID * HID; i += 128) Ws[i] = W2[i];
    __syncthreads();
    int nb = blockIdx.x * 64;
    int ng = threadIdx.x >> 3;
    int c8 = (threadIdx.x & 7) * 8;
    int n0 = nb + ng;
    const float* h0 = g_aggh + (size_t)min(n0,      NN - 1) * HID;
    const float* h1 = g_aggh + (size_t)min(n0 + 16, NN - 1) * HID;
    const float* h2 = g_aggh + (size_t)min(n0 + 32, NN - 1) * HID;
    const float* h3 = g_aggh + (size_t)min(n0 + 48, NN - 1) * HID;
    float a[4][8];
#pragma unroll
    for (int j = 0; j < 4; j++)
#pragma unroll
        for (int c = 0; c < 8; c++) a[j][c] = 0.f;
#pragma unroll 4
    for (int k = 0; k < HID; k++) {
        float4 w0 = *(const float4*)(Ws + k * HID + c8);
        float4 w1 = *(const float4*)(Ws + k * HID + c8 + 4);
        float hv[4] = {__ldg(h0 + k), __ldg(h1 + k), __ldg(h2 + k), __ldg(h3 + k)};
#pragma unroll
        for (int j = 0; j < 4; j++) {
            a[j][0] = fmaf(hv[j], w0.x, a[j][0]); a[j][1] = fmaf(hv[j], w0.y, a[j][1]);
            a[j][2] = fmaf(hv[j], w0.z, a[j][2]); a[j][3] = fmaf(hv[j], w0.w, a[j][3]);
            a[j][4] = fmaf(hv[j], w1.x, a[j][4]); a[j][5] = fmaf(hv[j], w1.y, a[j][5]);
            a[j][6] = fmaf(hv[j], w1.z, a[j][6]); a[j][7] = fmaf(hv[j], w1.w, a[j][7]);
        }
    }
    float4 bb0 = __ldg((const float4*)(b2 + c8));
    float4 bb1 = __ldg((const float4*)(b2 + c8 + 4));
#pragma unroll
    for (int j = 0; j < 4; j++) {
        int n = n0 + 16 * j;
        if (n < NN) {
            int g = __ldg(batch + n);
            float r0 = fmaxf(a[j][0] + bb0.x, 0.f);
            float r1 = fmaxf(a[j][1] + bb0.y, 0.f);
            float r2 = fmaxf(a[j][2] + bb0.z, 0.f);
            float r3 = fmaxf(a[j][3] + bb0.w, 0.f);
            float r4 = fmaxf(a[j][4] + bb1.x, 0.f);
            float r5 = fmaxf(a[j][5] + bb1.y, 0.f);
            float r6 = fmaxf(a[j][6] + bb1.z, 0.f);
            float r7 = fmaxf(a[j][7] + bb1.w, 0.f);
            red4(&g_pooled[g * HID + c8],     r0, r1, r2, r3);
            red4(&g_pooled[g * HID + c8 + 4], r4, r5, r6, r7);
        }
    }
}

// -------- final: out[g][o] = (pooled[g]@Wfc)[o]/cnt[g] + bfc[o] -----------
__global__ void k_final(const float* __restrict__ Wfc,
                        const float* __restrict__ bfc,
                        float* __restrict__ out) {
    int t = threadIdx.x;                // 512 threads: (g, o)
    int g = t >> 1, o = t & 1;
    float acc = 0.f;
#pragma unroll
    for (int c = 0; c < HID; c++)
        acc += g_pooled[g * HID + c] * __ldg(Wfc + c * 2 + o);
    float cnt = fmaxf(g_cnt[g], 1.0f);
    out[g * 2 + o] = acc / cnt + __ldg(bfc + o);
}

extern "C" void kernel_launch(void* const* d_in, const int* in_sizes, int n_in,
                              void* d_out, int out_size) {
    const float* x     = (const float*)d_in[0];
    const int*   ei    = (const int*)d_in[1];     // int32 (JAX x64 disabled)
    const int*   batch = (const int*)d_in[2];
    const float* W1    = (const float*)d_in[3];
    const float* b1    = (const float*)d_in[4];
    const float* W2    = (const float*)d_in[5];
    const float* b2    = (const float*)d_in[6];
    const float* Wfc   = (const float*)d_in[7];
    const float* bfc   = (const float*)d_in[8];
    float*       out   = (float*)d_out;

    const int* src = ei;
    const int* dst = ei + NE;

    const int T = 256;
    k_init<<<(NN + T - 1) / T, T>>>();
    k_degi<<<(NE + T - 1) / T, T>>>(dst);
    k_scan<<<NBLK, 256>>>(x, batch);
    k_scatter<<<(NE + T - 1) / T, T>>>(src, dst);
    k_aggx<<<(NN * 32) / 256, 256>>>();
    k_lin1<<<(NN * 8 + T - 1) / T, T>>>(W1, b1);
    k_aggh<<<(NN * 32) / 256, 256>>>();
    k_lin2pool<<<(NN + 63) / 64, 128>>>(W2, b2, batch);
    k_final<<<1, 512>>>(Wfc, bfc, out);
}

// round 17
// speedup vs baseline: 1.1385x; 1.1385x over previous
#include <cuda_runtime.h>
#include <cuda_fp16.h>
#include <cstdint>

#define NN 100000
#define NE 1200000
#define NG 256
#define HID 64
#define INC 5
#define NBLK ((NN + 255) / 256)

// -------- scratch (device globals; no allocation allowed) --------
__device__ __align__(256) __half g_xpre[NN * 8];     // dinv*x, 5 used of 8 halves
__device__ __align__(256) float  g_aggx[NN * 8];     // layer-1 aggregated input (5 used)
__device__ __align__(256) __half g_h1[NN * HID];     // h1pre = dinv*relu(lin1) fp16
__device__ __align__(256) float  g_aggh[NN * HID];   // layer-2 aggregated hidden
__device__ __align__(256) int    g_degi[NN];
__device__ __align__(256) int    g_rowptr[NN];
__device__ __align__(256) int    g_cursor[NN];
__device__ __align__(256) float  g_dinv[NN];
__device__ __align__(256) int    g_csri[NE];         // src per edge, dst-grouped
__device__ __align__(256) float  g_pooled[NG * HID];
__device__ __align__(256) float  g_cnt[NG];
__device__ int g_gbase;

__device__ __forceinline__ void red4(float* p, float a, float b, float c, float d) {
    asm volatile("red.global.add.v4.f32 [%0], {%1,%2,%3,%4};"
                 :: "l"(p), "f"(a), "f"(b), "f"(c), "f"(d) : "memory");
}

// -------- init --------
__global__ void k_init() {
    int i = blockIdx.x * blockDim.x + threadIdx.x;
    if (i < NN) g_degi[i] = 0;
    if (i < NG * HID) g_pooled[i] = 0.f;
    if (i < NG) g_cnt[i] = 0.f;
    if (i == 0) g_gbase = 0;
}

// -------- degree: 4 edges/thread, fire-and-forget (REDG path) --------
__global__ void k_degi4(const int* __restrict__ dst) {
    int t = blockIdx.x * blockDim.x + threadIdx.x;
    if (t >= NE / 4) return;
    int4 d = __ldg((const int4*)dst + t);
    atomicAdd(&g_degi[d.x], 1);
    atomicAdd(&g_degi[d.y], 1);
    atomicAdd(&g_degi[d.z], 1);
    atomicAdd(&g_degi[d.w], 1);
}

// -------- single-pass scan (block scan + atomic base) + node prep --------
__global__ void k_scan(const float* __restrict__ x, const int* __restrict__ batch) {
    __shared__ int sh[256];
    __shared__ int sbase;
    int i = blockIdx.x * 256 + threadIdx.x;
    int v = (i < NN) ? g_degi[i] : 0;
    sh[threadIdx.x] = v;
    __syncthreads();
    for (int off = 1; off < 256; off <<= 1) {
        int t = (threadIdx.x >= off) ? sh[threadIdx.x - off] : 0;
        __syncthreads();
        sh[threadIdx.x] += t;
        __syncthreads();
    }
    if (threadIdx.x == 255) sbase = atomicAdd(&g_gbase, sh[255]);
    __syncthreads();
    if (i >= NN) return;
    int r = sbase + sh[threadIdx.x] - v;
    g_rowptr[i] = r;
    g_cursor[i] = r;
    float di = rsqrtf((float)v + 1.0f);       // +1 = self-loop
    g_dinv[i] = di;
    const float* xr = x + i * INC;
    __half2 h0 = __floats2half2_rn(di * __ldg(xr + 0), di * __ldg(xr + 1));
    __half2 h1 = __floats2half2_rn(di * __ldg(xr + 2), di * __ldg(xr + 3));
    __half2 h2 = __floats2half2_rn(di * __ldg(xr + 4), 0.f);
    uint4 u;
    u.x = *(unsigned*)&h0; u.y = *(unsigned*)&h1;
    u.z = *(unsigned*)&h2; u.w = 0u;
    *(uint4*)(g_xpre + i * 8) = u;
    atomicAdd(&g_cnt[__ldg(batch + i)], 1.0f);
}

// -------- scatter edges into CSR slots (cursor atomic; proven form) --------
__global__ void k_scatter(const int* __restrict__ src, const int* __restrict__ dst) {
    int e = blockIdx.x * blockDim.x + threadIdx.x;
    if (e >= NE) return;
    int s = __ldg(src + e);
    int d = __ldg(dst + e);
    int slot = atomicAdd(&g_cursor[d], 1);
    g_csri[slot] = s;
}

__device__ __forceinline__ void acc5(uint4 u, float a[5]) {
    float2 f0 = __half22float2(*(__half2*)&u.x);
    float2 f1 = __half22float2(*(__half2*)&u.y);
    float2 f2 = __half22float2(*(__half2*)&u.z);
    a[0] += f0.x; a[1] += f0.y; a[2] += f1.x; a[3] += f1.y; a[4] += f2.x;
}

// -------- layer-1 aggregation: aggX = dinv*(sum xpre[src] + xpre[n]) ------
// One thread/node, 4-wide unrolled gather.
__global__ void k_aggx() {
    int n = blockIdx.x * blockDim.x + threadIdx.x;
    if (n >= NN) return;
    int i = g_rowptr[n];
    int end = i + g_degi[n];
    float a[5] = {0.f, 0.f, 0.f, 0.f, 0.f};
    for (; i + 4 <= end; i += 4) {
        int s0 = __ldg(g_csri + i);
        int s1 = __ldg(g_csri + i + 1);
        int s2 = __ldg(g_csri + i + 2);
        int s3 = __ldg(g_csri + i + 3);
        uint4 u0 = __ldg((const uint4*)(g_xpre + s0 * 8));
        uint4 u1 = __ldg((const uint4*)(g_xpre + s1 * 8));
        uint4 u2 = __ldg((const uint4*)(g_xpre + s2 * 8));
        uint4 u3 = __ldg((const uint4*)(g_xpre + s3 * 8));
        acc5(u0, a); acc5(u1, a); acc5(u2, a); acc5(u3, a);
    }
    for (; i < end; i++)
        acc5(__ldg((const uint4*)(g_xpre + __ldg(g_csri + i) * 8)), a);
    acc5(*(const uint4*)(g_xpre + n * 8), a);   // self term
    float di = g_dinv[n];
    float* o = g_aggx + n * 8;
    *(float4*)o = make_float4(di * a[0], di * a[1], di * a[2], di * a[3]);
    o[4] = di * a[4];
}

// -------- lin1: h1pre = dinv * relu(aggX @ W1 + b1) -> fp16; 8 ch/thread --
__global__ void k_lin1(const float* __restrict__ W1, const float* __restrict__ b1) {
    int idx = blockIdx.x * blockDim.x + threadIdx.x;   // NN*8 threads
    if (idx >= NN * 8) return;
    int n = idx >> 3, c8 = (idx & 7) * 8;
    float xr[INC];
#pragma unroll
    for (int k = 0; k < INC; k++) xr[k] = __ldg(g_aggx + n * 8 + k);
    float4 a0 = __ldg((const float4*)(b1 + c8));
    float4 a1 = __ldg((const float4*)(b1 + c8 + 4));
#pragma unroll
    for (int k = 0; k < INC; k++) {
        float4 w0 = __ldg((const float4*)(W1 + k * HID + c8));
        float4 w1 = __ldg((const float4*)(W1 + k * HID + c8 + 4));
        a0.x = fmaf(xr[k], w0.x, a0.x); a0.y = fmaf(xr[k], w0.y, a0.y);
        a0.z = fmaf(xr[k], w0.z, a0.z); a0.w = fmaf(xr[k], w0.w, a0.w);
        a1.x = fmaf(xr[k], w1.x, a1.x); a1.y = fmaf(xr[k], w1.y, a1.y);
        a1.z = fmaf(xr[k], w1.z, a1.z); a1.w = fmaf(xr[k], w1.w, a1.w);
    }
    float di = g_dinv[n];
    __half2 p0 = __floats2half2_rn(di * fmaxf(a0.x, 0.f), di * fmaxf(a0.y, 0.f));
    __half2 p1 = __floats2half2_rn(di * fmaxf(a0.z, 0.f), di * fmaxf(a0.w, 0.f));
    __half2 p2 = __floats2half2_rn(di * fmaxf(a1.x, 0.f), di * fmaxf(a1.y, 0.f));
    __half2 p3 = __floats2half2_rn(di * fmaxf(a1.z, 0.f), di * fmaxf(a1.w, 0.f));
    uint4 u;
    u.x = *(unsigned*)&p0; u.y = *(unsigned*)&p1;
    u.z = *(unsigned*)&p2; u.w = *(unsigned*)&p3;
    *(uint4*)(g_h1 + (size_t)n * HID + c8) = u;
}

__device__ __forceinline__ void acc8(uint4 u, float a[8]) {
    float2 f0 = __half22float2(*(__half2*)&u.x);
    float2 f1 = __half22float2(*(__half2*)&u.y);
    float2 f2 = __half22float2(*(__half2*)&u.z);
    float2 f3 = __half22float2(*(__half2*)&u.w);
    a[0] += f0.x; a[1] += f0.y; a[2] += f1.x; a[3] += f1.y;
    a[4] += f2.x; a[5] += f2.y; a[6] += f3.x; a[7] += f3.y;
}

// -------- layer-2 aggregation: aggH = dinv*(sum h1pre[src] + h1pre[n]) ----
// 8 lanes/node (R12 layout), 4-wide unrolled gather for MLP=4.
__global__ void k_aggh() {
    int t = blockIdx.x * blockDim.x + threadIdx.x;   // NN*8 threads
    int n = t >> 3;
    if (n >= NN) return;
    int l = (t & 7) * 8;
    int i = g_rowptr[n];
    int end = i + g_degi[n];
    float a[8] = {0.f, 0.f, 0.f, 0.f, 0.f, 0.f, 0.f, 0.f};
    for (; i + 4 <= end; i += 4) {
        int s0 = __ldg(g_csri + i);
        int s1 = __ldg(g_csri + i + 1);
        int s2 = __ldg(g_csri + i + 2);
        int s3 = __ldg(g_csri + i + 3);
        uint4 u0 = __ldg((const uint4*)(g_h1 + (size_t)s0 * HID + l));
        uint4 u1 = __ldg((const uint4*)(g_h1 + (size_t)s1 * HID + l));
        uint4 u2 = __ldg((const uint4*)(g_h1 + (size_t)s2 * HID + l));
        uint4 u3 = __ldg((const uint4*)(g_h1 + (size_t)s3 * HID + l));
        acc8(u0, a); acc8(u1, a); acc8(u2, a); acc8(u3, a);
    }
    for (; i < end; i++)
        acc8(__ldg((const uint4*)(g_h1 + (size_t)__ldg(g_csri + i) * HID + l)), a);
    acc8(*(const uint4*)(g_h1 + (size_t)n * HID + l), a);   // self
    float di = g_dinv[n];
    float* o = g_aggh + (size_t)n * HID + l;
    *(float4*)o       = make_float4(di * a[0], di * a[1], di * a[2], di * a[3]);
    *(float4*)(o + 4) = make_float4(di * a[4], di * a[5], di * a[6], di * a[7]);
}

// -------- lin2 fused with relu + mean-pool RED (no h2 buffer) -------------
__global__ void __launch_bounds__(128) k_lin2pool(const float* __restrict__ W2,
                                                  const float* __restrict__ b2,
                                                  const int* __restrict__ batch) {
    __shared__ float Ws[HID * HID];
    for (int i = threadIdx.x; i < HID * HID; i += 128) Ws[i] = W2[i];
    __syncthreads();
    int nb = blockIdx.x * 64;
    int ng = threadIdx.x >> 3;
    int c8 = (threadIdx.x & 7) * 8;
    int n0 = nb + ng;
    const float* h0 = g_aggh + (size_t)min(n0,      NN - 1) * HID;
    const float* h1 = g_aggh + (size_t)min(n0 + 16, NN - 1) * HID;
    const float* h2 = g_aggh + (size_t)min(n0 + 32, NN - 1) * HID;
    const float* h3 = g_aggh + (size_t)min(n0 + 48, NN - 1) * HID;
    float a[4][8];
#pragma unroll
    for (int j = 0; j < 4; j++)
#pragma unroll
        for (int c = 0; c < 8; c++) a[j][c] = 0.f;
#pragma unroll 4
    for (int k = 0; k < HID; k++) {
        float4 w0 = *(const float4*)(Ws + k * HID + c8);
        float4 w1 = *(const float4*)(Ws + k * HID + c8 + 4);
        float hv[4] = {__ldg(h0 + k), __ldg(h1 + k), __ldg(h2 + k), __ldg(h3 + k)};
#pragma unroll
        for (int j = 0; j < 4; j++) {
            a[j][0] = fmaf(hv[j], w0.x, a[j][0]); a[j][1] = fmaf(hv[j], w0.y, a[j][1]);
            a[j][2] = fmaf(hv[j], w0.z, a[j][2]); a[j][3] = fmaf(hv[j], w0.w, a[j][3]);
            a[j][4] = fmaf(hv[j], w1.x, a[j][4]); a[j][5] = fmaf(hv[j], w1.y, a[j][5]);
            a[j][6] = fmaf(hv[j], w1.z, a[j][6]); a[j][7] = fmaf(hv[j], w1.w, a[j][7]);
        }
    }
    float4 bb0 = __ldg((const float4*)(b2 + c8));
    float4 bb1 = __ldg((const float4*)(b2 + c8 + 4));
#pragma unroll
    for (int j = 0; j < 4; j++) {
        int n = n0 + 16 * j;
        if (n < NN) {
            int g = __ldg(batch + n);
            float r0 = fmaxf(a[j][0] + bb0.x, 0.f);
            float r1 = fmaxf(a[j][1] + bb0.y, 0.f);
            float r2 = fmaxf(a[j][2] + bb0.z, 0.f);
            float r3 = fmaxf(a[j][3] + bb0.w, 0.f);
            float r4 = fmaxf(a[j][4] + bb1.x, 0.f);
            float r5 = fmaxf(a[j][5] + bb1.y, 0.f);
            float r6 = fmaxf(a[j][6] + bb1.z, 0.f);
            float r7 = fmaxf(a[j][7] + bb1.w, 0.f);
            red4(&g_pooled[g * HID + c8],     r0, r1, r2, r3);
            red4(&g_pooled[g * HID + c8 + 4], r4, r5, r6, r7);
        }
    }
}

// -------- final: out[g][o] = (pooled[g]@Wfc)[o]/cnt[g] + bfc[o] -----------
__global__ void k_final(const float* __restrict__ Wfc,
                        const float* __restrict__ bfc,
                        float* __restrict__ out) {
    int t = threadIdx.x;                // 512 threads: (g, o)
    int g = t >> 1, o = t & 1;
    float acc = 0.f;
#pragma unroll
    for (int c = 0; c < HID; c++)
        acc += g_pooled[g * HID + c] * __ldg(Wfc + c * 2 + o);
    float cnt = fmaxf(g_cnt[g], 1.0f);
    out[g * 2 + o] = acc / cnt + __ldg(bfc + o);
}

extern "C" void kernel_launch(void* const* d_in, const int* in_sizes, int n_in,
                              void* d_out, int out_size) {
    const float* x     = (const float*)d_in[0];
    const int*   ei    = (const int*)d_in[1];     // int32 (JAX x64 disabled)
    const int*   batch = (const int*)d_in[2];
    const float* W1    = (const float*)d_in[3];
    const float* b1    = (const float*)d_in[4];
    const float* W2    = (const float*)d_in[5];
    const float* b2    = (const float*)d_in[6];
    const float* Wfc   = (const float*)d_in[7];
    const float* bfc   = (const float*)d_in[8];
    float*       out   = (float*)d_out;

    const int* src = ei;
    const int* dst = ei + NE;

    const int T = 256;
    k_init<<<(NN + T - 1) / T, T>>>();
    k_degi4<<<(NE / 4 + T - 1) / T, T>>>(dst);
    k_scan<<<NBLK, 256>>>(x, batch);
    k_scatter<<<(NE + T - 1) / T, T>>>(src, dst);
    k_aggx<<<(NN + T - 1) / T, T>>>();
    k_lin1<<<(NN * 8 + T - 1) / T, T>>>(W1, b1);
    k_aggh<<<(NN * 8 + T - 1) / T, T>>>();
    k_lin2pool<<<(NN + 63) / 64, 128>>>(W2, b2, batch);
    k_final<<<1, 512>>>(Wfc, bfc, out);
}